// round 16
// baseline (speedup 1.0000x reference)
#include <cuda_runtime.h>
#include <cstdint>
#include <math.h>

#define BB    64
#define NN    2048
#define DIM   768
#define POOL  1024
#define LEN   16
#define ROW   2080          // 2*LEN + NN
#define NCHUNK 32
#define CH    64            // NN / NCHUNK
#define D4    192           // DIM / 4
#define QSTR  193           // smem query row stride in float4
#define PBLK  64            // sim prompt-blocks (16 prompts each)
#define CHAIN_BLOCKS 128    // PBLK * 2 tiles
#define SQ_F4   (32 * QSTR)         // query tile float4 count
#define KT_F4   (16 * D4)           // key tile float4 count (3072)
#define SIM_SMEM ((SQ_F4 + 2 * KT_F4) * 16)   // 197120 bytes

// ---------------- scratch (device globals; only referenced in device code) --
__device__ __align__(16) float g_part[NCHUNK * BB * DIM];
__device__ __align__(16) float g_xnorm[BB * DIM];
__device__ float g_c1v[PBLK * BB];
__device__ int   g_c1i[PBLK * BB];
__device__ float g_c2v[PBLK * BB];
__device__ int   g_c2i[PBLK * BB];
__device__ int   g_idx[BB];
__device__ float g_maxsim[BB];
__device__ int   g_cnt_mean[BB];      // zero-init; self-resetting
__device__ int   g_bar[2];            // monotonic grid barriers (never reset)

__device__ __forceinline__ float warp_sum(float v) {
    #pragma unroll
    for (int o = 16; o > 0; o >>= 1) v += __shfl_xor_sync(0xffffffffu, v, o);
    return v;
}

__device__ __forceinline__ void warp_argmax(float& v, int& i) {
    #pragma unroll
    for (int o = 16; o > 0; o >>= 1) {
        float ov = __shfl_xor_sync(0xffffffffu, v, o);
        int   oi = __shfl_xor_sync(0xffffffffu, i, o);
        if (ov > v || (ov == v && oi < i)) { v = ov; i = oi; }
    }
}

__device__ __forceinline__ void reduce_cand(const float* cv, const int* ci,
                                            int b, int lane, float& v, int& i) {
    float va = cv[lane * BB + b];        int ia = ci[lane * BB + b];
    float vb = cv[(lane + 32) * BB + b]; int ib = ci[(lane + 32) * BB + b];
    if (vb > va || (vb == va && ib < ia)) { va = vb; ia = ib; }
    v = va; i = ia;
    warp_argmax(v, i);
}

// Monotonic grid barrier: epoch arithmetic makes it replay-safe with NO reset
// and NO exit barrier. All CHAIN_BLOCKS blocks co-resident (1 block/SM).
__device__ __forceinline__ void grid_bar(int id) {
    __syncthreads();
    if (threadIdx.x == 0) {
        __threadfence();
        int old = atomicAdd(&g_bar[id], 1);
        int target = old - (old % CHAIN_BLOCKS) + CHAIN_BLOCKS;
        while (*(volatile int*)&g_bar[id] < target) { }
        __threadfence();
    }
    __syncthreads();
}

__device__ __forceinline__ void cp_async16(unsigned int saddr, const void* gptr) {
    asm volatile("cp.async.cg.shared.global [%0], [%1], 16;" :: "r"(saddr), "l"(gptr));
}
__device__ __forceinline__ void cp_commit() {
    asm volatile("cp.async.commit_group;");
}

// ---------------------------------------------------------------------------
// K1: stream x_embed -> out[:, 32:, :] (write-through stores); partial sums;
// last block per b does mean+l2norm. grid (BB, NCHUNK), 192 threads.
// ---------------------------------------------------------------------------
__global__ void k_mean_copy(const float* __restrict__ x, float* __restrict__ out) {
    const int t = threadIdx.x;            // 0..191
    const int b = blockIdx.x;
    const int z = blockIdx.y;

    const float4* src = reinterpret_cast<const float4*>(
        x + ((size_t)b * NN + (size_t)z * CH) * DIM) + t;
    float4* dst = reinterpret_cast<float4*>(
        out + ((size_t)b * ROW + 2 * LEN + (size_t)z * CH) * DIM) + t;

    float4 s = make_float4(0.f, 0.f, 0.f, 0.f);
    for (int n0 = 0; n0 < CH; n0 += 8) {
        float4 v[8];
        #pragma unroll
        for (int k = 0; k < 8; k++)
            v[k] = __ldcs(src + (size_t)(n0 + k) * D4);
        #pragma unroll
        for (int k = 0; k < 8; k++) {
            s.x += v[k].x; s.y += v[k].y; s.z += v[k].z; s.w += v[k].w;
            __stwt(dst + (size_t)(n0 + k) * D4, v[k]);
        }
    }
    reinterpret_cast<float4*>(g_part)[((size_t)z * BB + b) * D4 + t] = s;

    __shared__ int s_last;
    __threadfence();
    __syncthreads();
    if (t == 0) {
        int old = atomicAdd(&g_cnt_mean[b], 1);
        s_last = (old == NCHUNK - 1);
    }
    __syncthreads();
    if (!s_last) return;
    __threadfence();

    const int w = t >> 5, lane = t & 31;
    float4 acc = make_float4(0.f, 0.f, 0.f, 0.f);
    #pragma unroll
    for (int z2 = 0; z2 < NCHUNK; z2++) {
        float4 p = reinterpret_cast<const float4*>(g_part)[((size_t)z2 * BB + b) * D4 + t];
        acc.x += p.x; acc.y += p.y; acc.z += p.z; acc.w += p.w;
    }
    const float inv = 1.0f / (float)NN;
    float4 v = make_float4(acc.x * inv, acc.y * inv, acc.z * inv, acc.w * inv);

    float ss = v.x * v.x + v.y * v.y + v.z * v.z + v.w * v.w;
    ss = warp_sum(ss);
    __shared__ float sm[6];
    __shared__ float s_rinv;
    if (lane == 0) sm[w] = ss;
    __syncthreads();
    if (t == 0) {
        float tot = 0.f;
        #pragma unroll
        for (int i = 0; i < 6; i++) tot += sm[i];
        s_rinv = 1.0f / sqrtf(fmaxf(tot, 1e-12f));
        g_cnt_mean[b] = 0;
    }
    __syncthreads();
    const float rinv = s_rinv;
    reinterpret_cast<float4*>(g_xnorm + (size_t)b * DIM)[t] =
        make_float4(v.x * rinv, v.y * rinv, v.z * rinv, v.w * rinv);
}

// ---------------------------------------------------------------------------
// sim core: keys resident in smem (ksm, 16 rows x 192 float4), queries in sq.
// ---------------------------------------------------------------------------
__device__ __forceinline__ void sim_core(const float4* __restrict__ ksm,
                                         const float4* __restrict__ sq,
                                         float* __restrict__ cv, int* __restrict__ ci,
                                         int pb, int bt, int t) {
    const int w = t >> 5, lane = t & 31;
    const float4* k0 = ksm + (size_t)(w * 2) * D4;
    const float4* k1 = k0 + D4;

    float s0 = 0.f, s1 = 0.f;
    #pragma unroll
    for (int jj = 0; jj < 6; jj++) {
        float4 a = k0[lane + 32 * jj];
        s0 += a.x * a.x + a.y * a.y + a.z * a.z + a.w * a.w;
        float4 c = k1[lane + 32 * jj];
        s1 += c.x * c.x + c.y * c.y + c.z * c.z + c.w * c.w;
    }
    s0 = warp_sum(s0); s1 = warp_sum(s1);
    const float r0 = 1.0f / sqrtf(fmaxf(s0, 1e-12f));
    const float r1 = 1.0f / sqrtf(fmaxf(s1, 1e-12f));

    const float4* q = sq + (size_t)lane * QSTR;
    float a0 = 0.f, a1 = 0.f, b0 = 0.f, b1 = 0.f;
    #pragma unroll 4
    for (int j = 0; j < D4; j++) {
        float4 ka = k0[j];
        float4 kb = k1[j];
        float4 qq = q[j];
        a0 += ka.x * qq.x + ka.y * qq.y;
        a1 += ka.z * qq.z + ka.w * qq.w;
        b0 += kb.x * qq.x + kb.y * qq.y;
        b1 += kb.z * qq.z + kb.w * qq.w;
    }
    const int p0 = pb * 16 + w * 2;
    const float v0 = r0 * (a0 + a1);
    const float v1 = r1 * (b0 + b1);

    float bv = v0; int bi = p0;
    if (v1 > v0) { bv = v1; bi = p0 + 1; }

    __shared__ float cvs[8][32];
    __shared__ int   cis[8][32];
    cvs[w][lane] = bv; cis[w][lane] = bi;
    __syncthreads();
    if (w == 0) {
        float best = cvs[0][lane]; int besti = cis[0][lane];
        #pragma unroll
        for (int i = 1; i < 8; i++) {
            float ov = cvs[i][lane]; int oi = cis[i][lane];
            if (ov > best || (ov == best && oi < besti)) { best = ov; besti = oi; }
        }
        const int b = bt * 32 + lane;
        cv[pb * BB + b] = best; ci[pb * BB + b] = besti;
    }
    __syncthreads();
}

// ---------------------------------------------------------------------------
// K2: whole chain, 2 monotonic grid barriers, no exit barrier.
// grid (PBLK, 2), 256 threads, 1 block/SM.
// ---------------------------------------------------------------------------
__global__ void k_chain(const float* __restrict__ pk,
                        const float* __restrict__ rpk,
                        const float* __restrict__ prompt,
                        const float* __restrict__ rprompt,
                        float* __restrict__ out,
                        long long out_size) {
    const int pb = blockIdx.x;
    const int bt = blockIdx.y;
    const int t = threadIdx.x;
    const int w = t >> 5, lane = t & 31;
    const int gid = bt * PBLK + pb;

    extern __shared__ char smem_raw[];
    float4* sq  = reinterpret_cast<float4*>(smem_raw);              // queries
    float4* kp  = sq + SQ_F4;                                       // pk tile
    float4* krp = kp + KT_F4;                                       // rpk tile
    __shared__ int s_idxs[32];

    // Async key staging: group A = pk tile, group B = rpk tile.
    {
        const float4* srcp = reinterpret_cast<const float4*>(pk  + (size_t)pb * 16 * DIM);
        const float4* srcr = reinterpret_cast<const float4*>(rpk + (size_t)pb * 16 * DIM);
        unsigned int kp_s  = (unsigned int)__cvta_generic_to_shared(kp);
        unsigned int krp_s = (unsigned int)__cvta_generic_to_shared(krp);
        #pragma unroll
        for (int i = t; i < KT_F4; i += 256) cp_async16(kp_s + i * 16, srcp + i);
        cp_commit();
        #pragma unroll
        for (int i = t; i < KT_F4; i += 256) cp_async16(krp_s + i * 16, srcr + i);
        cp_commit();
    }

    // Level-1 query tile (g_xnorm rows, L2-hot)
    for (int i = t; i < 32 * D4; i += 256) {
        const int r = i / D4, c = i % D4;
        sq[r * QSTR + c] =
            reinterpret_cast<const float4*>(g_xnorm + (size_t)(bt * 32 + r) * DIM)[c];
    }
    asm volatile("cp.async.wait_group 1;");   // pk tile resident
    __syncthreads();

    // Phase 1: level-1 sim
    sim_core(kp, sq, g_c1v, g_c1i, pb, bt, t);
    grid_bar(0);

    // Phase 2: every block self-reduces level-1 candidates for its tile;
    // pb==0 publishes g_idx/g_maxsim.
    #pragma unroll
    for (int k = 0; k < 4; k++) {
        const int bloc = w * 4 + k;
        const int b = bt * 32 + bloc;
        float v; int i;
        reduce_cand(g_c1v, g_c1i, b, lane, v, i);
        if (lane == 0) {
            s_idxs[bloc] = i;
            if (pb == 0) { g_idx[b] = i; g_maxsim[b] = v; }
        }
    }
    __syncthreads();

    // Build residual queries in place: sq[r] = pk[idx[r]] - sq[r]  (pk L2-hot)
    for (int i = t; i < 32 * D4; i += 256) {
        const int r = i / D4, c = i % D4;
        float4 a = reinterpret_cast<const float4*>(pk + (size_t)s_idxs[r] * DIM)[c];
        float4 xn = sq[r * QSTR + c];
        sq[r * QSTR + c] = make_float4(a.x - xn.x, a.y - xn.y, a.z - xn.z, a.w - xn.w);
    }
    asm volatile("cp.async.wait_group 0;");   // rpk tile resident (long done)
    __syncthreads();

    // Phase 3: level-2 sim
    sim_core(krp, sq, g_c2v, g_c2i, pb, bt, t);
    grid_bar(1);

    // Phase 4: reduce level-2 candidates, gather both prompts, scalar loss
    {
        const int b = gid >> 1;
        const int half = gid & 1;
        __shared__ int s_ridx;
        if (t < 32) {
            float v; int i;
            reduce_cand(g_c2v, g_c2i, b, lane, v, i);
            if (lane == 0) s_ridx = i;
        }
        __syncthreads();
        const int SEG = LEN * DIM / 4;    // 3072
        float4* dst = reinterpret_cast<float4*>(out + (size_t)b * ROW * DIM);
        if (half == 0) {
            const float4* s1 = reinterpret_cast<const float4*>(
                rprompt + (size_t)s_ridx * LEN * DIM);
            #pragma unroll 4
            for (int i = t; i < SEG; i += 256) dst[i] = s1[i];
        } else {
            const float4* s2 = reinterpret_cast<const float4*>(
                prompt + (size_t)s_idxs[b & 31] * LEN * DIM);
            #pragma unroll 4
            for (int i = t; i < SEG; i += 256) dst[SEG + i] = s2[i];
        }

        if (gid == 0) {
            __shared__ float psum[64];
            if (t < 64) {
                float v = g_c2v[t]; int i = g_c2i[t];
                #pragma unroll 8
                for (int pbk = 1; pbk < PBLK; pbk++) {
                    float ov = g_c2v[pbk * BB + t]; int oi = g_c2i[pbk * BB + t];
                    if (ov > v || (ov == v && oi < i)) { v = ov; i = oi; }
                }
                psum[t] = g_maxsim[t] + v;
            }
            __syncthreads();
            if (t == 0) {
                float s = 0.f;
                #pragma unroll
                for (int i = 0; i < 64; i++) s += psum[i];
                s *= (1.0f / (float)BB);
                const size_t np = (size_t)BB * ROW * DIM;
                if ((size_t)out_size > np) out[(size_t)out_size - 1] = s;
            }
        }
    }
    // no exit barrier needed: monotonic barriers are replay-safe without reset
}

// ---------------------------------------------------------------------------
extern "C" void kernel_launch(void* const* d_in, const int* in_sizes, int n_in,
                              void* d_out, int out_size) {
    const float* x       = (const float*)d_in[0];
    const float* prompt  = (const float*)d_in[1];
    const float* pk      = (const float*)d_in[2];
    const float* rprompt = (const float*)d_in[3];
    const float* rpk     = (const float*)d_in[4];
    float* out = (float*)d_out;

    static int attr_done = 0;
    if (!attr_done) {
        cudaFuncSetAttribute(k_chain, cudaFuncAttributeMaxDynamicSharedMemorySize, SIM_SMEM);
        attr_done = 1;
    }

    k_mean_copy<<<dim3(BB, NCHUNK), D4>>>(x, out);
    k_chain<<<dim3(PBLK, 2), 256, SIM_SMEM>>>(pk, rpk, prompt, rprompt,
                                              out, (long long)out_size);
}

// round 17
// speedup vs baseline: 1.0124x; 1.0124x over previous
#include <cuda_runtime.h>
#include <cstdint>
#include <math.h>

#define BB    64
#define NN    2048
#define DIM   768
#define POOL  1024
#define LEN   16
#define ROW   2080          // 2*LEN + NN
#define NCHUNK 32
#define CH    64            // NN / NCHUNK
#define D4    192           // DIM / 4
#define QSTR  193           // smem query row stride in float4
#define PBLK  64            // sim prompt-blocks (16 prompts each)
#define CHAIN_BLOCKS 128    // PBLK * 2 tiles
#define SQ_F4   (32 * QSTR)         // query tile float4 count
#define KT_F4   (16 * D4)           // key tile float4 count (3072)
#define SIM_SMEM ((SQ_F4 + 2 * KT_F4) * 16)   // 197120 bytes

// ---------------- scratch (device globals; only referenced in device code) --
__device__ __align__(16) float g_part[NCHUNK * BB * DIM];
__device__ __align__(16) float g_xnorm[BB * DIM];
__device__ float g_c1v[PBLK * BB];
__device__ int   g_c1i[PBLK * BB];
__device__ float g_c2v[PBLK * BB];
__device__ int   g_c2i[PBLK * BB];
__device__ int   g_idx[BB];
__device__ float g_maxsim[BB];
__device__ int   g_cnt_mean[BB];      // zero-init; self-resetting
__device__ int   g_bar[2];            // monotonic grid barriers (never reset)
__device__ int   g_fin;               // monotonic xnorm-finalizer counter
__device__ int   g_ready;             // 0/1 handshake copy -> chain

__device__ __forceinline__ float warp_sum(float v) {
    #pragma unroll
    for (int o = 16; o > 0; o >>= 1) v += __shfl_xor_sync(0xffffffffu, v, o);
    return v;
}

__device__ __forceinline__ void warp_argmax(float& v, int& i) {
    #pragma unroll
    for (int o = 16; o > 0; o >>= 1) {
        float ov = __shfl_xor_sync(0xffffffffu, v, o);
        int   oi = __shfl_xor_sync(0xffffffffu, i, o);
        if (ov > v || (ov == v && oi < i)) { v = ov; i = oi; }
    }
}

__device__ __forceinline__ void reduce_cand(const float* cv, const int* ci,
                                            int b, int lane, float& v, int& i) {
    float va = cv[lane * BB + b];        int ia = ci[lane * BB + b];
    float vb = cv[(lane + 32) * BB + b]; int ib = ci[(lane + 32) * BB + b];
    if (vb > va || (vb == va && ib < ia)) { va = vb; ia = ib; }
    v = va; i = ia;
    warp_argmax(v, i);
}

// Monotonic grid barrier: replay-safe with no reset. 1 block/SM co-residency.
__device__ __forceinline__ void grid_bar(int id) {
    __syncthreads();
    if (threadIdx.x == 0) {
        __threadfence();
        int old = atomicAdd(&g_bar[id], 1);
        int target = old - (old % CHAIN_BLOCKS) + CHAIN_BLOCKS;
        while (*(volatile int*)&g_bar[id] < target) { }
        __threadfence();
    }
    __syncthreads();
}

__device__ __forceinline__ void cp_async16(unsigned int saddr, const void* gptr) {
    asm volatile("cp.async.cg.shared.global [%0], [%1], 16;" :: "r"(saddr), "l"(gptr));
}
__device__ __forceinline__ void cp_commit() {
    asm volatile("cp.async.commit_group;");
}

// ---------------------------------------------------------------------------
// K1: stream x_embed -> out[:, 32:, :]; partial sums; last block per b does
// mean+l2norm; the 64th finalizer raises g_ready for the concurrent chain.
// grid (BB, NCHUNK), 192 threads.
// ---------------------------------------------------------------------------
__global__ void k_mean_copy(const float* __restrict__ x, float* __restrict__ out) {
    const int t = threadIdx.x;            // 0..191
    const int b = blockIdx.x;
    const int z = blockIdx.y;

    const float4* src = reinterpret_cast<const float4*>(
        x + ((size_t)b * NN + (size_t)z * CH) * DIM) + t;
    float4* dst = reinterpret_cast<float4*>(
        out + ((size_t)b * ROW + 2 * LEN + (size_t)z * CH) * DIM) + t;

    float4 s = make_float4(0.f, 0.f, 0.f, 0.f);
    for (int n0 = 0; n0 < CH; n0 += 8) {
        float4 v[8];
        #pragma unroll
        for (int k = 0; k < 8; k++)
            v[k] = __ldcs(src + (size_t)(n0 + k) * D4);
        #pragma unroll
        for (int k = 0; k < 8; k++) {
            s.x += v[k].x; s.y += v[k].y; s.z += v[k].z; s.w += v[k].w;
            __stcs(dst + (size_t)(n0 + k) * D4, v[k]);
        }
    }
    reinterpret_cast<float4*>(g_part)[((size_t)z * BB + b) * D4 + t] = s;

    __shared__ int s_last;
    __threadfence();
    __syncthreads();
    if (t == 0) {
        int old = atomicAdd(&g_cnt_mean[b], 1);
        s_last = (old == NCHUNK - 1);
    }
    __syncthreads();
    if (!s_last) return;
    __threadfence();

    const int w = t >> 5, lane = t & 31;
    float4 acc = make_float4(0.f, 0.f, 0.f, 0.f);
    #pragma unroll
    for (int z2 = 0; z2 < NCHUNK; z2++) {
        float4 p = reinterpret_cast<const float4*>(g_part)[((size_t)z2 * BB + b) * D4 + t];
        acc.x += p.x; acc.y += p.y; acc.z += p.z; acc.w += p.w;
    }
    const float inv = 1.0f / (float)NN;
    float4 v = make_float4(acc.x * inv, acc.y * inv, acc.z * inv, acc.w * inv);

    float ss = v.x * v.x + v.y * v.y + v.z * v.z + v.w * v.w;
    ss = warp_sum(ss);
    __shared__ float sm[6];
    __shared__ float s_rinv;
    if (lane == 0) sm[w] = ss;
    __syncthreads();
    if (t == 0) {
        float tot = 0.f;
        #pragma unroll
        for (int i = 0; i < 6; i++) tot += sm[i];
        s_rinv = 1.0f / sqrtf(fmaxf(tot, 1e-12f));
        g_cnt_mean[b] = 0;
    }
    __syncthreads();
    const float rinv = s_rinv;
    reinterpret_cast<float4*>(g_xnorm + (size_t)b * DIM)[t] =
        make_float4(v.x * rinv, v.y * rinv, v.z * rinv, v.w * rinv);

    // release: xnorm visible, then the 64th finalizer raises the ready flag
    __threadfence();
    __syncthreads();
    if (t == 0) {
        int old = atomicAdd(&g_fin, 1);
        if ((old % BB) == BB - 1) atomicAdd(&g_ready, 1);
    }
}

// ---------------------------------------------------------------------------
// sim core: keys resident in smem (ksm, 16 rows x 192 float4), queries in sq.
// ---------------------------------------------------------------------------
__device__ __forceinline__ void sim_core(const float4* __restrict__ ksm,
                                         const float4* __restrict__ sq,
                                         float* __restrict__ cv, int* __restrict__ ci,
                                         int pb, int bt, int t) {
    const int w = t >> 5, lane = t & 31;
    const float4* k0 = ksm + (size_t)(w * 2) * D4;
    const float4* k1 = k0 + D4;

    float s0 = 0.f, s1 = 0.f;
    #pragma unroll
    for (int jj = 0; jj < 6; jj++) {
        float4 a = k0[lane + 32 * jj];
        s0 += a.x * a.x + a.y * a.y + a.z * a.z + a.w * a.w;
        float4 c = k1[lane + 32 * jj];
        s1 += c.x * c.x + c.y * c.y + c.z * c.z + c.w * c.w;
    }
    s0 = warp_sum(s0); s1 = warp_sum(s1);
    const float r0 = 1.0f / sqrtf(fmaxf(s0, 1e-12f));
    const float r1 = 1.0f / sqrtf(fmaxf(s1, 1e-12f));

    const float4* q = sq + (size_t)lane * QSTR;
    float a0 = 0.f, a1 = 0.f, b0 = 0.f, b1 = 0.f;
    #pragma unroll 4
    for (int j = 0; j < D4; j++) {
        float4 ka = k0[j];
        float4 kb = k1[j];
        float4 qq = q[j];
        a0 += ka.x * qq.x + ka.y * qq.y;
        a1 += ka.z * qq.z + ka.w * qq.w;
        b0 += kb.x * qq.x + kb.y * qq.y;
        b1 += kb.z * qq.z + kb.w * qq.w;
    }
    const int p0 = pb * 16 + w * 2;
    const float v0 = r0 * (a0 + a1);
    const float v1 = r1 * (b0 + b1);

    float bv = v0; int bi = p0;
    if (v1 > v0) { bv = v1; bi = p0 + 1; }

    __shared__ float cvs[8][32];
    __shared__ int   cis[8][32];
    cvs[w][lane] = bv; cis[w][lane] = bi;
    __syncthreads();
    if (w == 0) {
        float best = cvs[0][lane]; int besti = cis[0][lane];
        #pragma unroll
        for (int i = 1; i < 8; i++) {
            float ov = cvs[i][lane]; int oi = cis[i][lane];
            if (ov > best || (ov == best && oi < besti)) { best = ov; besti = oi; }
        }
        const int b = bt * 32 + lane;
        cv[pb * BB + b] = best; ci[pb * BB + b] = besti;
    }
    __syncthreads();
}

// ---------------------------------------------------------------------------
// K2: whole chain; launched CONCURRENTLY with the copy on a forked stream.
// Stages keys via cp.async immediately, then spins on g_ready (set by the
// copy's last xnorm finalizer). grid (PBLK, 2), 256 threads, 1 block/SM.
// ---------------------------------------------------------------------------
__global__ void k_chain(const float* __restrict__ pk,
                        const float* __restrict__ rpk,
                        const float* __restrict__ prompt,
                        const float* __restrict__ rprompt,
                        float* __restrict__ out,
                        long long out_size) {
    const int pb = blockIdx.x;
    const int bt = blockIdx.y;
    const int t = threadIdx.x;
    const int w = t >> 5, lane = t & 31;
    const int gid = bt * PBLK + pb;

    extern __shared__ char smem_raw[];
    float4* sq  = reinterpret_cast<float4*>(smem_raw);              // queries
    float4* kp  = sq + SQ_F4;                                       // pk tile
    float4* krp = kp + KT_F4;                                       // rpk tile
    __shared__ int s_idxs[32];

    // Async key staging (no dependency on the copy) — overlaps with it.
    {
        const float4* srcp = reinterpret_cast<const float4*>(pk  + (size_t)pb * 16 * DIM);
        const float4* srcr = reinterpret_cast<const float4*>(rpk + (size_t)pb * 16 * DIM);
        unsigned int kp_s  = (unsigned int)__cvta_generic_to_shared(kp);
        unsigned int krp_s = (unsigned int)__cvta_generic_to_shared(krp);
        #pragma unroll
        for (int i = t; i < KT_F4; i += 256) cp_async16(kp_s + i * 16, srcp + i);
        cp_commit();
        #pragma unroll
        for (int i = t; i < KT_F4; i += 256) cp_async16(krp_s + i * 16, srcr + i);
        cp_commit();
    }

    // Wait for the copy kernel to publish g_xnorm (acquire).
    if (t == 0) {
        while (*(volatile int*)&g_ready == 0) { }
        __threadfence();
    }
    __syncthreads();

    // Level-1 query tile (g_xnorm rows, L2-hot)
    for (int i = t; i < 32 * D4; i += 256) {
        const int r = i / D4, c = i % D4;
        sq[r * QSTR + c] =
            reinterpret_cast<const float4*>(g_xnorm + (size_t)(bt * 32 + r) * DIM)[c];
    }
    asm volatile("cp.async.wait_group 1;");   // pk tile resident
    __syncthreads();

    // Phase 1: level-1 sim
    sim_core(kp, sq, g_c1v, g_c1i, pb, bt, t);
    grid_bar(0);

    // Consume the ready flag exactly once per replay (all blocks passed spin).
    if (gid == 0 && t == 0) atomicSub(&g_ready, 1);

    // Phase 2: every block self-reduces level-1 candidates for its tile;
    // pb==0 publishes g_idx/g_maxsim.
    #pragma unroll
    for (int k = 0; k < 4; k++) {
        const int bloc = w * 4 + k;
        const int b = bt * 32 + bloc;
        float v; int i;
        reduce_cand(g_c1v, g_c1i, b, lane, v, i);
        if (lane == 0) {
            s_idxs[bloc] = i;
            if (pb == 0) { g_idx[b] = i; g_maxsim[b] = v; }
        }
    }
    __syncthreads();

    // Build residual queries in place: sq[r] = pk[idx[r]] - sq[r]  (pk L2-hot)
    for (int i = t; i < 32 * D4; i += 256) {
        const int r = i / D4, c = i % D4;
        float4 a = reinterpret_cast<const float4*>(pk + (size_t)s_idxs[r] * DIM)[c];
        float4 xn = sq[r * QSTR + c];
        sq[r * QSTR + c] = make_float4(a.x - xn.x, a.y - xn.y, a.z - xn.z, a.w - xn.w);
    }
    asm volatile("cp.async.wait_group 0;");   // rpk tile resident (long done)
    __syncthreads();

    // Phase 3: level-2 sim
    sim_core(krp, sq, g_c2v, g_c2i, pb, bt, t);
    grid_bar(1);

    // Phase 4: reduce level-2 candidates, gather both prompts, scalar loss
    {
        const int b = gid >> 1;
        const int half = gid & 1;
        __shared__ int s_ridx;
        if (t < 32) {
            float v; int i;
            reduce_cand(g_c2v, g_c2i, b, lane, v, i);
            if (lane == 0) s_ridx = i;
        }
        __syncthreads();
        const int SEG = LEN * DIM / 4;    // 3072
        float4* dst = reinterpret_cast<float4*>(out + (size_t)b * ROW * DIM);
        if (half == 0) {
            const float4* s1 = reinterpret_cast<const float4*>(
                rprompt + (size_t)s_ridx * LEN * DIM);
            #pragma unroll 4
            for (int i = t; i < SEG; i += 256) dst[i] = s1[i];
        } else {
            const float4* s2 = reinterpret_cast<const float4*>(
                prompt + (size_t)s_idxs[b & 31] * LEN * DIM);
            #pragma unroll 4
            for (int i = t; i < SEG; i += 256) dst[SEG + i] = s2[i];
        }

        if (gid == 0) {
            __shared__ float psum[64];
            if (t < 64) {
                float v = g_c2v[t]; int i = g_c2i[t];
                #pragma unroll 8
                for (int pbk = 1; pbk < PBLK; pbk++) {
                    float ov = g_c2v[pbk * BB + t]; int oi = g_c2i[pbk * BB + t];
                    if (ov > v || (ov == v && oi < i)) { v = ov; i = oi; }
                }
                psum[t] = g_maxsim[t] + v;
            }
            __syncthreads();
            if (t == 0) {
                float s = 0.f;
                #pragma unroll
                for (int i = 0; i < 64; i++) s += psum[i];
                s *= (1.0f / (float)BB);
                const size_t np = (size_t)BB * ROW * DIM;
                if ((size_t)out_size > np) out[(size_t)out_size - 1] = s;
            }
        }
    }
}

// ---------------------------------------------------------------------------
extern "C" void kernel_launch(void* const* d_in, const int* in_sizes, int n_in,
                              void* d_out, int out_size) {
    const float* x       = (const float*)d_in[0];
    const float* prompt  = (const float*)d_in[1];
    const float* pk      = (const float*)d_in[2];
    const float* rprompt = (const float*)d_in[3];
    const float* rpk     = (const float*)d_in[4];
    float* out = (float*)d_out;

    static cudaStream_t s2 = 0;
    static cudaEvent_t ev_fork = 0, ev_join = 0;
    if (!s2) {
        cudaStreamCreateWithFlags(&s2, cudaStreamNonBlocking);
        cudaEventCreateWithFlags(&ev_fork, cudaEventDisableTiming);
        cudaEventCreateWithFlags(&ev_join, cudaEventDisableTiming);
        cudaFuncSetAttribute(k_chain, cudaFuncAttributeMaxDynamicSharedMemorySize, SIM_SMEM);
    }

    // Fork: chain is a SIBLING of the copy (device-side handshake via g_ready).
    cudaEventRecord(ev_fork, 0);
    cudaStreamWaitEvent(s2, ev_fork, 0);

    k_mean_copy<<<dim3(BB, NCHUNK), D4>>>(x, out);
    k_chain<<<dim3(PBLK, 2), 256, SIM_SMEM, s2>>>(pk, rpk, prompt, rprompt,
                                                  out, (long long)out_size);

    // Join back into the capture stream.
    cudaEventRecord(ev_join, s2);
    cudaStreamWaitEvent((cudaStream_t)0, ev_join, 0);
}